// round 10
// baseline (speedup 1.0000x reference)
#include <cuda_runtime.h>
#include <cuda_bf16.h>
#include <cstdint>

#define N_NODE 100000
#define N_EDGE 1600000
#define D      128
#define DE     16
#define FULLM  0xFFFFFFFFu
#define NBLK   98          // ceil(N_NODE / 1024)

// ---------------------------------------------------------------------------
// Scratch (static device arrays; allocation is forbidden)
// ---------------------------------------------------------------------------
__device__ int    g_cnt[N_NODE];
__device__ int    g_rowtmp[N_NODE];
__device__ int    g_bsum[NBLK];
__device__ int    g_bpre[NBLK];
__device__ int    g_rowoff[N_NODE + 1];
__device__ int    g_cur[N_NODE];
__device__ int2   g_slot[N_EDGE];             // (src_node, weight_bits)
__device__ float4 g_eagg[N_NODE * (DE / 4)];  // 6.4 MB
__device__ float4 g_h[(N_NODE + 128) * (D / 4)]; // fused pre-MLP activations

// ---------------------------------------------------------------------------
// f32x2 packed-FMA helpers (Blackwell FFMA2; bit-identical fp32 semantics)
// ---------------------------------------------------------------------------
__device__ __forceinline__ unsigned long long pack2(float a, float b)
{
    unsigned long long r;
    asm("mov.b64 %0, {%1, %2};" : "=l"(r) : "f"(a), "f"(b));
    return r;
}
__device__ __forceinline__ float2 unpack2(unsigned long long v)
{
    float2 r;
    asm("mov.b64 {%0, %1}, %2;" : "=f"(r.x), "=f"(r.y) : "l"(v));
    return r;
}
__device__ __forceinline__ void ffma2(unsigned long long& d,
                                      unsigned long long a,
                                      unsigned long long b)
{
    asm("fma.rn.f32x2 %0, %1, %2, %0;" : "+l"(d) : "l"(a), "l"(b));
}
__device__ __forceinline__ void red_add_v4(float4* addr, float4 v)
{
    asm volatile("red.global.add.v4.f32 [%0], {%1, %2, %3, %4};"
                 :: "l"(addr), "f"(v.x), "f"(v.y), "f"(v.z), "f"(v.w)
                 : "memory");
}

// ---------------------------------------------------------------------------
// K1: histogram of destination nodes
// ---------------------------------------------------------------------------
__global__ __launch_bounds__(256) void k_hist(const int2* __restrict__ edge_list)
{
    int e = blockIdx.x * blockDim.x + threadIdx.x;
    if (e < N_EDGE) atomicAdd(&g_cnt[edge_list[e].y], 1);
}

// ---------------------------------------------------------------------------
// K2a/b/c: 3-phase coalesced exclusive scan
// ---------------------------------------------------------------------------
__global__ __launch_bounds__(1024) void k_scan1()
{
    __shared__ int sdata[1024];
    int t = threadIdx.x, b = blockIdx.x;
    int idx = b * 1024 + t;
    int v = (idx < N_NODE) ? g_cnt[idx] : 0;
    sdata[t] = v;
    __syncthreads();
    for (int off = 1; off < 1024; off <<= 1) {
        int u = (t >= off) ? sdata[t - off] : 0;
        __syncthreads();
        sdata[t] += u;
        __syncthreads();
    }
    if (idx < N_NODE) g_rowtmp[idx] = sdata[t] - v;   // exclusive
    if (t == 1023) g_bsum[b] = sdata[1023];
}

__global__ __launch_bounds__(128) void k_scan2()
{
    __shared__ int sdata[128];
    int t = threadIdx.x;
    int v = (t < NBLK) ? g_bsum[t] : 0;
    sdata[t] = v;
    __syncthreads();
    for (int off = 1; off < 128; off <<= 1) {
        int u = (t >= off) ? sdata[t - off] : 0;
        __syncthreads();
        sdata[t] += u;
        __syncthreads();
    }
    if (t < NBLK) g_bpre[t] = sdata[t] - v;
    if (t == 127) g_rowoff[N_NODE] = sdata[127];
}

__global__ __launch_bounds__(1024) void k_scan3()
{
    int idx = blockIdx.x * 1024 + threadIdx.x;
    if (idx < N_NODE) {
        int r = g_rowtmp[idx] + g_bpre[idx >> 10];
        g_rowoff[idx] = r;
        g_cur[idx]    = r;
    }
}

// ---------------------------------------------------------------------------
// K3: reorder edges into CSR slots + accumulate edge_agg
// ---------------------------------------------------------------------------
__global__ __launch_bounds__(256) void k_reorder(
    const int2*  __restrict__ edge_list,
    const float* __restrict__ edge_weight,
    const float* __restrict__ edge_feat)
{
    int e = blockIdx.x * blockDim.x + threadIdx.x;
    if (e >= N_EDGE) return;
    int2  nn = edge_list[e];
    float w  = edge_weight[e];
    int slot = atomicAdd(&g_cur[nn.y], 1);
    g_slot[slot] = make_int2(nn.x, __float_as_int(w));

    const float4* fr = (const float4*)(edge_feat + (size_t)e * DE);
    #pragma unroll
    for (int i = 0; i < DE / 4; i++) {
        float4 f = fr[i];
        f.x *= w; f.y *= w; f.z *= w; f.w *= w;
        red_add_v4(&g_eagg[(size_t)nn.y * (DE / 4) + i], f);
    }
}

// ---------------------------------------------------------------------------
// K4: gather-reduce.  One warp per node, edge loop unrolled x4.
//   h[node] = x[node] + sum_e w*x[src] + eagg[node] @ W_edge + b_edge
// ---------------------------------------------------------------------------
__global__ __launch_bounds__(256) void k_gather(
    const float* __restrict__ x,
    const float* __restrict__ We,   // (16, 128)
    const float* __restrict__ be)   // (128,)
{
    const int node = blockIdx.x * 8 + (threadIdx.x >> 5);
    const int lane = threadIdx.x & 31;

    const float4* x4  = (const float4*)x;
    const float4* We4 = (const float4*)We;
    const float4* be4 = (const float4*)be;

    const int s = g_rowoff[node];
    const int e = g_rowoff[node + 1];

    float4 acc = make_float4(0.f, 0.f, 0.f, 0.f);

    int j = s;
    for (; j + 4 <= e; j += 4) {
        int2 s0 = g_slot[j + 0];
        int2 s1 = g_slot[j + 1];
        int2 s2 = g_slot[j + 2];
        int2 s3 = g_slot[j + 3];
        float4 v0 = x4[(size_t)s0.x * (D / 4) + lane];
        float4 v1 = x4[(size_t)s1.x * (D / 4) + lane];
        float4 v2 = x4[(size_t)s2.x * (D / 4) + lane];
        float4 v3 = x4[(size_t)s3.x * (D / 4) + lane];
        float w0 = __int_as_float(s0.y);
        float w1 = __int_as_float(s1.y);
        float w2 = __int_as_float(s2.y);
        float w3 = __int_as_float(s3.y);
        acc.x += w0 * v0.x + w1 * v1.x + w2 * v2.x + w3 * v3.x;
        acc.y += w0 * v0.y + w1 * v1.y + w2 * v2.y + w3 * v3.y;
        acc.z += w0 * v0.z + w1 * v1.z + w2 * v2.z + w3 * v3.z;
        acc.w += w0 * v0.w + w1 * v1.w + w2 * v2.w + w3 * v3.w;
    }
    for (; j < e; j++) {
        int2 sv = g_slot[j];
        float w = __int_as_float(sv.y);
        float4 v = x4[(size_t)sv.x * (D / 4) + lane];
        acc.x += w * v.x; acc.y += w * v.y;
        acc.z += w * v.z; acc.w += w * v.w;
    }

    // eagg @ W_edge: eagg row in lanes 0..3 (lane sl holds k = 4*sl + c)
    float4 ea = make_float4(0.f, 0.f, 0.f, 0.f);
    if (lane < (DE / 4)) ea = g_eagg[(size_t)node * (DE / 4) + lane];
    #pragma unroll
    for (int sl = 0; sl < 4; sl++) {
        float e0 = __shfl_sync(FULLM, ea.x, sl);
        float e1 = __shfl_sync(FULLM, ea.y, sl);
        float e2 = __shfl_sync(FULLM, ea.z, sl);
        float e3 = __shfl_sync(FULLM, ea.w, sl);
        float4 w0 = We4[(4 * sl + 0) * (D / 4) + lane];
        float4 w1 = We4[(4 * sl + 1) * (D / 4) + lane];
        float4 w2 = We4[(4 * sl + 2) * (D / 4) + lane];
        float4 w3 = We4[(4 * sl + 3) * (D / 4) + lane];
        acc.x += e0 * w0.x + e1 * w1.x + e2 * w2.x + e3 * w3.x;
        acc.y += e0 * w0.y + e1 * w1.y + e2 * w2.y + e3 * w3.y;
        acc.z += e0 * w0.z + e1 * w1.z + e2 * w2.z + e3 * w3.z;
        acc.w += e0 * w0.w + e1 * w1.w + e2 * w2.w + e3 * w3.w;
    }

    float4 xs = x4[(size_t)node * (D / 4) + lane];
    float4 bb = be4[lane];
    acc.x += xs.x + bb.x; acc.y += xs.y + bb.y;
    acc.z += xs.z + bb.z; acc.w += xs.w + bb.w;
    g_h[(size_t)node * (D / 4) + lane] = acc;
}

// ---------------------------------------------------------------------------
// K5: node MLP with packed f32x2 FMAs (R4 inner loop, wider tile).
// 96 nodes/block, 768 threads (24 warps), 4 nodes x 4 cols per thread.
// ---------------------------------------------------------------------------
#define SH_STRIDE 132
#define MLP_NODES 96
#define MLP_THREADS 768

__global__ __launch_bounds__(MLP_THREADS, 1) void k_mlp(
    const float* __restrict__ W1,
    const float* __restrict__ b1,
    const float* __restrict__ W2,
    const float* __restrict__ b2,
    float* __restrict__ out)
{
    extern __shared__ float smem[];
    float* sW1 = smem;                 // 16384 floats
    float* sW2 = sW1 + 16384;          // 16384 floats
    float* sh  = sW2 + 16384;          // 96 * 132 floats

    const int tid  = threadIdx.x;
    const int base = blockIdx.x * MLP_NODES;

    {
        const float4* W1v = (const float4*)W1;
        const float4* W2v = (const float4*)W2;
        float4* sW1v = (float4*)sW1;
        float4* sW2v = (float4*)sW2;
        for (int i = tid; i < 4096; i += MLP_THREADS) { sW1v[i] = W1v[i]; sW2v[i] = W2v[i]; }
        // activation tile (g_h is padded past N_NODE, loads always in-bounds)
        for (int i = tid; i < MLP_NODES * 32; i += MLP_THREADS) {
            int n = i >> 5, c4 = i & 31;
            *(float4*)(sh + n * SH_STRIDE + c4 * 4) = g_h[(size_t)(base + n) * 32 + c4];
        }
    }
    __syncthreads();

    const int tx   = tid & 31;
    const int ty   = tid >> 5;       // 0..23
    const int col  = tx * 4;
    const int nrow = ty * 4;

    unsigned long long acc2[4][2];

    // ---- Layer 1 ----
    {
        const float4 bb = *(const float4*)(b1 + col);
        unsigned long long c01 = pack2(bb.x, bb.y);
        unsigned long long c23 = pack2(bb.z, bb.w);
        #pragma unroll
        for (int a = 0; a < 4; a++) { acc2[a][0] = c01; acc2[a][1] = c23; }
    }
    #pragma unroll 4
    for (int k = 0; k < 128; k++) {
        const ulonglong2 wv = *(const ulonglong2*)(sW1 + k * 128 + col);
        float h0 = sh[(nrow + 0) * SH_STRIDE + k];
        float h1 = sh[(nrow + 1) * SH_STRIDE + k];
        float h2 = sh[(nrow + 2) * SH_STRIDE + k];
        float h3 = sh[(nrow + 3) * SH_STRIDE + k];
        unsigned long long p0 = pack2(h0, h0);
        unsigned long long p1 = pack2(h1, h1);
        unsigned long long p2 = pack2(h2, h2);
        unsigned long long p3 = pack2(h3, h3);
        ffma2(acc2[0][0], p0, wv.x); ffma2(acc2[0][1], p0, wv.y);
        ffma2(acc2[1][0], p1, wv.x); ffma2(acc2[1][1], p1, wv.y);
        ffma2(acc2[2][0], p2, wv.x); ffma2(acc2[2][1], p2, wv.y);
        ffma2(acc2[3][0], p3, wv.x); ffma2(acc2[3][1], p3, wv.y);
    }
    __syncthreads();
    #pragma unroll
    for (int a = 0; a < 4; a++) {
        float2 q0 = unpack2(acc2[a][0]);
        float2 q1 = unpack2(acc2[a][1]);
        float4 r;
        r.x = fmaxf(q0.x, 0.f); r.y = fmaxf(q0.y, 0.f);
        r.z = fmaxf(q1.x, 0.f); r.w = fmaxf(q1.y, 0.f);
        *(float4*)(sh + (nrow + a) * SH_STRIDE + col) = r;
    }
    __syncthreads();

    // ---- Layer 2 ----
    {
        const float4 bb = *(const float4*)(b2 + col);
        unsigned long long c01 = pack2(bb.x, bb.y);
        unsigned long long c23 = pack2(bb.z, bb.w);
        #pragma unroll
        for (int a = 0; a < 4; a++) { acc2[a][0] = c01; acc2[a][1] = c23; }
    }
    #pragma unroll 4
    for (int k = 0; k < 128; k++) {
        const ulonglong2 wv = *(const ulonglong2*)(sW2 + k * 128 + col);
        float h0 = sh[(nrow + 0) * SH_STRIDE + k];
        float h1 = sh[(nrow + 1) * SH_STRIDE + k];
        float h2 = sh[(nrow + 2) * SH_STRIDE + k];
        float h3 = sh[(nrow + 3) * SH_STRIDE + k];
        unsigned long long p0 = pack2(h0, h0);
        unsigned long long p1 = pack2(h1, h1);
        unsigned long long p2 = pack2(h2, h2);
        unsigned long long p3 = pack2(h3, h3);
        ffma2(acc2[0][0], p0, wv.x); ffma2(acc2[0][1], p0, wv.y);
        ffma2(acc2[1][0], p1, wv.x); ffma2(acc2[1][1], p1, wv.y);
        ffma2(acc2[2][0], p2, wv.x); ffma2(acc2[2][1], p2, wv.y);
        ffma2(acc2[3][0], p3, wv.x); ffma2(acc2[3][1], p3, wv.y);
    }

    #pragma unroll
    for (int a = 0; a < 4; a++) {
        int node = base + nrow + a;
        if (node < N_NODE) {
            float2 q0 = unpack2(acc2[a][0]);
            float2 q1 = unpack2(acc2[a][1]);
            float4 r;
            r.x = fmaxf(q0.x, 0.f); r.y = fmaxf(q0.y, 0.f);
            r.z = fmaxf(q1.x, 0.f); r.w = fmaxf(q1.y, 0.f);
            *(float4*)(out + (size_t)node * D + col) = r;
        }
    }
}

// ---------------------------------------------------------------------------
// Launch
// ---------------------------------------------------------------------------
extern "C" void kernel_launch(void* const* d_in, const int* in_sizes, int n_in,
                              void* d_out, int out_size)
{
    const int2*  edge_list   = (const int2*)d_in[0];
    const float* edge_weight = (const float*)d_in[1];
    const float* edge_feat   = (const float*)d_in[2];
    // d_in[3] = num_node (constant)
    const float* x  = (const float*)d_in[4];
    const float* We = (const float*)d_in[5];
    const float* be = (const float*)d_in[6];
    const float* W1 = (const float*)d_in[7];
    const float* b1 = (const float*)d_in[8];
    const float* W2 = (const float*)d_in[9];
    const float* b2 = (const float*)d_in[10];
    float* out = (float*)d_out;

    const int smem_bytes = (16384 * 2 + MLP_NODES * SH_STRIDE) * 4;
    cudaFuncSetAttribute(k_mlp, cudaFuncAttributeMaxDynamicSharedMemorySize, smem_bytes);

    // Zero g_cnt + g_eagg via HW memset (g_cur is initialized by k_scan3)
    void* p_cnt  = nullptr;
    void* p_eagg = nullptr;
    cudaGetSymbolAddress(&p_cnt,  g_cnt);
    cudaGetSymbolAddress(&p_eagg, g_eagg);
    cudaMemsetAsync(p_cnt,  0, sizeof(int) * N_NODE);
    cudaMemsetAsync(p_eagg, 0, sizeof(float4) * N_NODE * (DE / 4));

    k_hist<<<(N_EDGE + 255) / 256, 256>>>(edge_list);
    k_scan1<<<NBLK, 1024>>>();
    k_scan2<<<1, 128>>>();
    k_scan3<<<NBLK, 1024>>>();
    k_reorder<<<(N_EDGE + 255) / 256, 256>>>(edge_list, edge_weight, edge_feat);
    k_gather<<<N_NODE / 8, 256>>>(x, We, be);

    const int nblk_mlp = (N_NODE + MLP_NODES - 1) / MLP_NODES;
    k_mlp<<<nblk_mlp, MLP_THREADS, smem_bytes>>>(W1, b1, W2, b2, out);
}

// round 11
// speedup vs baseline: 1.0280x; 1.0280x over previous
#include <cuda_runtime.h>
#include <cuda_bf16.h>
#include <cstdint>

#define N_NODE 100000
#define N_EDGE 1600000
#define D      128
#define DE     16
#define FULLM  0xFFFFFFFFu
#define NBLK   98          // ceil(N_NODE / 1024)

// ---------------------------------------------------------------------------
// Scratch (static device arrays; allocation is forbidden)
// ---------------------------------------------------------------------------
__device__ int    g_cnt[N_NODE];
__device__ int    g_rank[N_EDGE];             // per-edge insertion rank
__device__ int    g_rowtmp[N_NODE + 1];       // block-local exclusive prefix
__device__ int    g_bsum[NBLK];
__device__ int    g_bpre[NBLK];
__device__ int2   g_slot[N_EDGE];             // (src_node, weight_bits)
__device__ float4 g_eagg[N_NODE * (DE / 4)];  // 6.4 MB
__device__ float4 g_h[(N_NODE + 64) * (D / 4)]; // fused pre-MLP activations

// ---------------------------------------------------------------------------
// f32x2 packed-FMA helpers (Blackwell FFMA2; bit-identical fp32 semantics)
// ---------------------------------------------------------------------------
__device__ __forceinline__ unsigned long long pack2(float a, float b)
{
    unsigned long long r;
    asm("mov.b64 %0, {%1, %2};" : "=l"(r) : "f"(a), "f"(b));
    return r;
}
__device__ __forceinline__ float2 unpack2(unsigned long long v)
{
    float2 r;
    asm("mov.b64 {%0, %1}, %2;" : "=f"(r.x), "=f"(r.y) : "l"(v));
    return r;
}
__device__ __forceinline__ void ffma2(unsigned long long& d,
                                      unsigned long long a,
                                      unsigned long long b)
{
    asm("fma.rn.f32x2 %0, %1, %2, %0;" : "+l"(d) : "l"(a), "l"(b));
}
__device__ __forceinline__ void red_add_v4(float4* addr, float4 v)
{
    asm volatile("red.global.add.v4.f32 [%0], {%1, %2, %3, %4};"
                 :: "l"(addr), "f"(v.x), "f"(v.y), "f"(v.z), "f"(v.w)
                 : "memory");
}

// ---------------------------------------------------------------------------
// K1: histogram of destination nodes + per-edge rank
// ---------------------------------------------------------------------------
__global__ __launch_bounds__(256) void k_hist(const int2* __restrict__ edge_list)
{
    int e = blockIdx.x * blockDim.x + threadIdx.x;
    if (e < N_EDGE)
        g_rank[e] = atomicAdd(&g_cnt[edge_list[e].y], 1);
}

// ---------------------------------------------------------------------------
// K2a: per-1024-block exclusive scan (+ fold g_eagg zeroing in)
// ---------------------------------------------------------------------------
__global__ __launch_bounds__(1024) void k_scan1()
{
    __shared__ int sdata[1024];
    int t = threadIdx.x, b = blockIdx.x;
    int idx = b * 1024 + t;
    int v = (idx < N_NODE) ? g_cnt[idx] : 0;
    sdata[t] = v;

    // zero this node's eagg row (4 x float4, contiguous 64B per thread)
    if (idx < N_NODE) {
        const float4 z = make_float4(0.f, 0.f, 0.f, 0.f);
        float4* ez = &g_eagg[(size_t)idx * (DE / 4)];
        ez[0] = z; ez[1] = z; ez[2] = z; ez[3] = z;
    }
    __syncthreads();
    for (int off = 1; off < 1024; off <<= 1) {
        int u = (t >= off) ? sdata[t - off] : 0;
        __syncthreads();
        sdata[t] += u;
        __syncthreads();
    }
    if (idx < N_NODE) g_rowtmp[idx] = sdata[t] - v;   // exclusive within block
    if (t == 1023) g_bsum[b] = sdata[1023];
}

// ---------------------------------------------------------------------------
// K2b: scan of block sums + sentinel
// ---------------------------------------------------------------------------
__global__ __launch_bounds__(128) void k_scan2()
{
    __shared__ int sdata[128];
    int t = threadIdx.x;
    int v = (t < NBLK) ? g_bsum[t] : 0;
    sdata[t] = v;
    __syncthreads();
    for (int off = 1; off < 128; off <<= 1) {
        int u = (t >= off) ? sdata[t - off] : 0;
        __syncthreads();
        sdata[t] += u;
        __syncthreads();
    }
    if (t < NBLK) g_bpre[t] = sdata[t] - v;
    // sentinel: rowtmp[N_NODE] + bpre[N_NODE>>10] == N_EDGE
    if (t == (N_NODE >> 10)) {
        int bpre_here = sdata[t] - v;
        g_rowtmp[N_NODE] = sdata[127] - bpre_here;
    }
}

// ---------------------------------------------------------------------------
// K3: reorder edges into CSR slots + accumulate edge_agg (rank-based, no atomics)
// ---------------------------------------------------------------------------
__global__ __launch_bounds__(256) void k_reorder(
    const int2*  __restrict__ edge_list,
    const float* __restrict__ edge_weight,
    const float* __restrict__ edge_feat)
{
    int e = blockIdx.x * blockDim.x + threadIdx.x;
    if (e >= N_EDGE) return;
    int2  nn = edge_list[e];
    float w  = edge_weight[e];
    int slot = g_rowtmp[nn.y] + g_bpre[nn.y >> 10] + g_rank[e];
    g_slot[slot] = make_int2(nn.x, __float_as_int(w));

    const float4* fr = (const float4*)(edge_feat + (size_t)e * DE);
    #pragma unroll
    for (int i = 0; i < DE / 4; i++) {
        float4 f = fr[i];
        f.x *= w; f.y *= w; f.z *= w; f.w *= w;
        red_add_v4(&g_eagg[(size_t)nn.y * (DE / 4) + i], f);
    }
}

// ---------------------------------------------------------------------------
// K4: gather-reduce.  One warp per node, edge loop unrolled x4.
//   h[node] = x[node] + sum_e w*x[src] + eagg[node] @ W_edge + b_edge
// ---------------------------------------------------------------------------
__global__ __launch_bounds__(256) void k_gather(
    const float* __restrict__ x,
    const float* __restrict__ We,   // (16, 128)
    const float* __restrict__ be)   // (128,)
{
    const int node = blockIdx.x * 8 + (threadIdx.x >> 5);
    const int lane = threadIdx.x & 31;

    const float4* x4  = (const float4*)x;
    const float4* We4 = (const float4*)We;
    const float4* be4 = (const float4*)be;

    const int s = g_rowtmp[node]     + g_bpre[node >> 10];
    const int e = g_rowtmp[node + 1] + g_bpre[(node + 1) >> 10];

    float4 acc = make_float4(0.f, 0.f, 0.f, 0.f);

    int j = s;
    for (; j + 4 <= e; j += 4) {
        int2 s0 = g_slot[j + 0];
        int2 s1 = g_slot[j + 1];
        int2 s2 = g_slot[j + 2];
        int2 s3 = g_slot[j + 3];
        float4 v0 = x4[(size_t)s0.x * (D / 4) + lane];
        float4 v1 = x4[(size_t)s1.x * (D / 4) + lane];
        float4 v2 = x4[(size_t)s2.x * (D / 4) + lane];
        float4 v3 = x4[(size_t)s3.x * (D / 4) + lane];
        float w0 = __int_as_float(s0.y);
        float w1 = __int_as_float(s1.y);
        float w2 = __int_as_float(s2.y);
        float w3 = __int_as_float(s3.y);
        acc.x += w0 * v0.x + w1 * v1.x + w2 * v2.x + w3 * v3.x;
        acc.y += w0 * v0.y + w1 * v1.y + w2 * v2.y + w3 * v3.y;
        acc.z += w0 * v0.z + w1 * v1.z + w2 * v2.z + w3 * v3.z;
        acc.w += w0 * v0.w + w1 * v1.w + w2 * v2.w + w3 * v3.w;
    }
    for (; j < e; j++) {
        int2 sv = g_slot[j];
        float w = __int_as_float(sv.y);
        float4 v = x4[(size_t)sv.x * (D / 4) + lane];
        acc.x += w * v.x; acc.y += w * v.y;
        acc.z += w * v.z; acc.w += w * v.w;
    }

    // eagg @ W_edge: eagg row in lanes 0..3 (lane sl holds k = 4*sl + c)
    float4 ea = make_float4(0.f, 0.f, 0.f, 0.f);
    if (lane < (DE / 4)) ea = g_eagg[(size_t)node * (DE / 4) + lane];
    #pragma unroll
    for (int sl = 0; sl < 4; sl++) {
        float e0 = __shfl_sync(FULLM, ea.x, sl);
        float e1 = __shfl_sync(FULLM, ea.y, sl);
        float e2 = __shfl_sync(FULLM, ea.z, sl);
        float e3 = __shfl_sync(FULLM, ea.w, sl);
        float4 w0 = We4[(4 * sl + 0) * (D / 4) + lane];
        float4 w1 = We4[(4 * sl + 1) * (D / 4) + lane];
        float4 w2 = We4[(4 * sl + 2) * (D / 4) + lane];
        float4 w3 = We4[(4 * sl + 3) * (D / 4) + lane];
        acc.x += e0 * w0.x + e1 * w1.x + e2 * w2.x + e3 * w3.x;
        acc.y += e0 * w0.y + e1 * w1.y + e2 * w2.y + e3 * w3.y;
        acc.z += e0 * w0.z + e1 * w1.z + e2 * w2.z + e3 * w3.z;
        acc.w += e0 * w0.w + e1 * w1.w + e2 * w2.w + e3 * w3.w;
    }

    float4 xs = x4[(size_t)node * (D / 4) + lane];
    float4 bb = be4[lane];
    acc.x += xs.x + bb.x; acc.y += xs.y + bb.y;
    acc.z += xs.z + bb.z; acc.w += xs.w + bb.w;
    g_h[(size_t)node * (D / 4) + lane] = acc;
}

// ---------------------------------------------------------------------------
// K5: node MLP with packed f32x2 FMAs (proven R4/R9 version).
// 64 nodes/block, 512 threads, 4 nodes x 4 cols per thread.
// ---------------------------------------------------------------------------
#define SH_STRIDE 132

__global__ __launch_bounds__(512, 1) void k_mlp(
    const float* __restrict__ W1,
    const float* __restrict__ b1,
    const float* __restrict__ W2,
    const float* __restrict__ b2,
    float* __restrict__ out)
{
    extern __shared__ float smem[];
    float* sW1 = smem;                 // 16384 floats
    float* sW2 = sW1 + 16384;          // 16384 floats
    float* sh  = sW2 + 16384;          // 64 * 132 floats

    const int tid  = threadIdx.x;
    const int base = blockIdx.x * 64;

    {
        const float4* W1v = (const float4*)W1;
        const float4* W2v = (const float4*)W2;
        float4* sW1v = (float4*)sW1;
        float4* sW2v = (float4*)sW2;
        #pragma unroll 4
        for (int i = tid; i < 4096; i += 512) { sW1v[i] = W1v[i]; sW2v[i] = W2v[i]; }
        // activation tile (g_h is padded past N_NODE, loads always in-bounds)
        for (int i = tid; i < 64 * 32; i += 512) {
            int n = i >> 5, c4 = i & 31;
            *(float4*)(sh + n * SH_STRIDE + c4 * 4) = g_h[(size_t)(base + n) * 32 + c4];
        }
    }
    __syncthreads();

    const int tx   = tid & 31;
    const int ty   = tid >> 5;       // 0..15
    const int col  = tx * 4;
    const int nrow = ty * 4;

    unsigned long long acc2[4][2];

    // ---- Layer 1 ----
    {
        const float4 bb = *(const float4*)(b1 + col);
        unsigned long long c01 = pack2(bb.x, bb.y);
        unsigned long long c23 = pack2(bb.z, bb.w);
        #pragma unroll
        for (int a = 0; a < 4; a++) { acc2[a][0] = c01; acc2[a][1] = c23; }
    }
    #pragma unroll 4
    for (int k = 0; k < 128; k++) {
        const ulonglong2 wv = *(const ulonglong2*)(sW1 + k * 128 + col);
        float h0 = sh[(nrow + 0) * SH_STRIDE + k];
        float h1 = sh[(nrow + 1) * SH_STRIDE + k];
        float h2 = sh[(nrow + 2) * SH_STRIDE + k];
        float h3 = sh[(nrow + 3) * SH_STRIDE + k];
        unsigned long long p0 = pack2(h0, h0);
        unsigned long long p1 = pack2(h1, h1);
        unsigned long long p2 = pack2(h2, h2);
        unsigned long long p3 = pack2(h3, h3);
        ffma2(acc2[0][0], p0, wv.x); ffma2(acc2[0][1], p0, wv.y);
        ffma2(acc2[1][0], p1, wv.x); ffma2(acc2[1][1], p1, wv.y);
        ffma2(acc2[2][0], p2, wv.x); ffma2(acc2[2][1], p2, wv.y);
        ffma2(acc2[3][0], p3, wv.x); ffma2(acc2[3][1], p3, wv.y);
    }
    __syncthreads();
    #pragma unroll
    for (int a = 0; a < 4; a++) {
        float2 q0 = unpack2(acc2[a][0]);
        float2 q1 = unpack2(acc2[a][1]);
        float4 r;
        r.x = fmaxf(q0.x, 0.f); r.y = fmaxf(q0.y, 0.f);
        r.z = fmaxf(q1.x, 0.f); r.w = fmaxf(q1.y, 0.f);
        *(float4*)(sh + (nrow + a) * SH_STRIDE + col) = r;
    }
    __syncthreads();

    // ---- Layer 2 ----
    {
        const float4 bb = *(const float4*)(b2 + col);
        unsigned long long c01 = pack2(bb.x, bb.y);
        unsigned long long c23 = pack2(bb.z, bb.w);
        #pragma unroll
        for (int a = 0; a < 4; a++) { acc2[a][0] = c01; acc2[a][1] = c23; }
    }
    #pragma unroll 4
    for (int k = 0; k < 128; k++) {
        const ulonglong2 wv = *(const ulonglong2*)(sW2 + k * 128 + col);
        float h0 = sh[(nrow + 0) * SH_STRIDE + k];
        float h1 = sh[(nrow + 1) * SH_STRIDE + k];
        float h2 = sh[(nrow + 2) * SH_STRIDE + k];
        float h3 = sh[(nrow + 3) * SH_STRIDE + k];
        unsigned long long p0 = pack2(h0, h0);
        unsigned long long p1 = pack2(h1, h1);
        unsigned long long p2 = pack2(h2, h2);
        unsigned long long p3 = pack2(h3, h3);
        ffma2(acc2[0][0], p0, wv.x); ffma2(acc2[0][1], p0, wv.y);
        ffma2(acc2[1][0], p1, wv.x); ffma2(acc2[1][1], p1, wv.y);
        ffma2(acc2[2][0], p2, wv.x); ffma2(acc2[2][1], p2, wv.y);
        ffma2(acc2[3][0], p3, wv.x); ffma2(acc2[3][1], p3, wv.y);
    }

    #pragma unroll
    for (int a = 0; a < 4; a++) {
        int node = base + nrow + a;
        if (node < N_NODE) {
            float2 q0 = unpack2(acc2[a][0]);
            float2 q1 = unpack2(acc2[a][1]);
            float4 r;
            r.x = fmaxf(q0.x, 0.f); r.y = fmaxf(q0.y, 0.f);
            r.z = fmaxf(q1.x, 0.f); r.w = fmaxf(q1.y, 0.f);
            *(float4*)(out + (size_t)node * D + col) = r;
        }
    }
}

// ---------------------------------------------------------------------------
// Launch.  Order chosen so ncu (-s 5 -c 1) captures k_gather (6th launch).
// ---------------------------------------------------------------------------
extern "C" void kernel_launch(void* const* d_in, const int* in_sizes, int n_in,
                              void* d_out, int out_size)
{
    const int2*  edge_list   = (const int2*)d_in[0];
    const float* edge_weight = (const float*)d_in[1];
    const float* edge_feat   = (const float*)d_in[2];
    // d_in[3] = num_node (constant)
    const float* x  = (const float*)d_in[4];
    const float* We = (const float*)d_in[5];
    const float* be = (const float*)d_in[6];
    const float* W1 = (const float*)d_in[7];
    const float* b1 = (const float*)d_in[8];
    const float* W2 = (const float*)d_in[9];
    const float* b2 = (const float*)d_in[10];
    float* out = (float*)d_out;

    const int smem_bytes = (16384 * 2 + 64 * SH_STRIDE) * 4;
    cudaFuncSetAttribute(k_mlp, cudaFuncAttributeMaxDynamicSharedMemorySize, smem_bytes);

    void* p_cnt = nullptr;
    cudaGetSymbolAddress(&p_cnt, g_cnt);
    cudaMemsetAsync(p_cnt, 0, sizeof(int) * N_NODE);        // launch 1

    k_hist<<<(N_EDGE + 255) / 256, 256>>>(edge_list);        // launch 2
    k_scan1<<<NBLK, 1024>>>();                               // launch 3 (also zeroes g_eagg)
    k_scan2<<<1, 128>>>();                                   // launch 4
    k_reorder<<<(N_EDGE + 255) / 256, 256>>>(edge_list, edge_weight, edge_feat); // launch 5
    k_gather<<<N_NODE / 8, 256>>>(x, We, be);                // launch 6 <- profiled
    k_mlp<<<(N_NODE + 63) / 64, 512, smem_bytes>>>(W1, b1, W2, b2, out);         // launch 7
}